// round 1
// baseline (speedup 1.0000x reference)
#include <cuda_runtime.h>

// ---------------------------------------------------------------------------
// GATConv: rst[src] += softmax_dst(leaky_relu(e_l[src]+e_r[dst])) * Zp[dst]
// Shapes: N=50000 nodes, E=1.6M edges, IN=128, OUT=32, HEADS=4 (OUT*H = 128)
// ---------------------------------------------------------------------------

#define NMAX 50000
#define EMAX 1600000
#define OH 128   // OUT_SIZE * HEADS

// ---- scratch (static device globals; no runtime allocation allowed) -------
__device__ float    g_Zp[(size_t)NMAX * OH];   // projected features  25.6 MB
__device__ float    g_el[NMAX * 4];            // per-node left logits  [N,H]
__device__ float    g_er[NMAX * 4];            // per-node right logits [N,H]
__device__ unsigned g_m [NMAX * 4];            // segment max (ordered-uint enc)
__device__ float    g_s [NMAX * 4];            // segment sum
__device__ float4   g_a [EMAX];                // per-edge logits -> exp values
__device__ int      g_is64;                    // index dtype flag

// ---- helpers ---------------------------------------------------------------
__device__ __forceinline__ unsigned enc_ord(float f) {
    unsigned u = __float_as_uint(f);
    return (u & 0x80000000u) ? ~u : (u | 0x80000000u);
}
__device__ __forceinline__ float dec_ord(unsigned u) {
    return __uint_as_float((u & 0x80000000u) ? (u & 0x7FFFFFFFu) : ~u);
}
__device__ __forceinline__ long long ld_idx(const void* idx, long long i, int is64) {
    if (is64) return ((const long long*)idx)[i];
    return (long long)((const int*)idx)[i];
}
__device__ __forceinline__ float4 wred_sum(float4 v) {
#pragma unroll
    for (int o = 16; o; o >>= 1) {
        v.x += __shfl_xor_sync(0xffffffffu, v.x, o);
        v.y += __shfl_xor_sync(0xffffffffu, v.y, o);
        v.z += __shfl_xor_sync(0xffffffffu, v.z, o);
        v.w += __shfl_xor_sync(0xffffffffu, v.w, o);
    }
    return v;
}

// ---- K-1: detect index width (int64 stored little-endian, values < 2^31) ---
__global__ void k_detect(const int* w, int nwords) {
    int ok = 1;
    for (int i = 1; i < nwords; i += 2)
        if (w[i] != 0) { ok = 0; break; }
    g_is64 = ok;
}

// ---- K0: zero the accumulators ---------------------------------------------
__global__ void k_init(float* out, int N) {
    int i = blockIdx.x * blockDim.x + threadIdx.x;
    int stride = gridDim.x * blockDim.x;
    int tot = N * OH;
    for (int j = i; j < tot; j += stride) out[j] = 0.0f;
    int tot2 = N * 4;
    for (int j = i; j < tot2; j += stride) { g_m[j] = 0u; g_s[j] = 0.0f; }
}

// ---- K1: Zp = Z @ W^T + b  (+ fused e_l, e_r) -------------------------------
// Block: 512 threads, 64 nodes x 128 cols output tile.
// SMEM: Wt[128][132] (W transposed, k-major) + Zt[128][68] (Z tile transposed).
// Thread (wrp = tid/32, lane = tid%32): 4 nodes (4*wrp..) x 4 cols (4*lane..).
// Column c maps to (o = c/4, h = c%4); lane == o, so e_l/e_r reduce over the warp.
#define WTS 132
#define ZTS 68
__global__ void k_gemm(const float* __restrict__ Z, const float* __restrict__ W,
                       const float* __restrict__ b, const float* __restrict__ al,
                       const float* __restrict__ ar, int N) {
    extern __shared__ float sm[];
    float* Wt = sm;                  // 128*132 floats
    float* Zt = sm + 128 * WTS;      // 128*68 floats

    const int tid  = threadIdx.x;
    const int kc   = tid & 31;       // k-group (4 k's each)
    const int g    = tid >> 5;       // 0..15
    const int node0 = blockIdx.x * 64;

    // load W transposed: Wt[k][c] = W[c][k]
    for (int c = g; c < 128; c += 16) {
        float4 w4 = *(const float4*)(W + c * 128 + kc * 4);
        Wt[(4 * kc + 0) * WTS + c] = w4.x;
        Wt[(4 * kc + 1) * WTS + c] = w4.y;
        Wt[(4 * kc + 2) * WTS + c] = w4.z;
        Wt[(4 * kc + 3) * WTS + c] = w4.w;
    }
    // load Z tile transposed: Zt[k][r] = Z[node0+r][k]
    for (int r = g; r < 64; r += 16) {
        int row = node0 + r; if (row >= N) row = N - 1;
        float4 z4 = *(const float4*)(Z + (size_t)row * 128 + kc * 4);
        Zt[(4 * kc + 0) * ZTS + r] = z4.x;
        Zt[(4 * kc + 1) * ZTS + r] = z4.y;
        Zt[(4 * kc + 2) * ZTS + r] = z4.z;
        Zt[(4 * kc + 3) * ZTS + r] = z4.w;
    }
    __syncthreads();

    const int lane = tid & 31;
    const int wrp  = tid >> 5;
    float4 acc[4];
#pragma unroll
    for (int n = 0; n < 4; n++) acc[n] = make_float4(0.f, 0.f, 0.f, 0.f);

    const float* wrow = Wt + 4 * lane;
    const float* zrow = Zt + 4 * wrp;
#pragma unroll 4
    for (int k = 0; k < 128; k++) {
        float4 wa = *(const float4*)(wrow + k * WTS);
        float4 za = *(const float4*)(zrow + k * ZTS);
        acc[0].x += za.x * wa.x; acc[0].y += za.x * wa.y; acc[0].z += za.x * wa.z; acc[0].w += za.x * wa.w;
        acc[1].x += za.y * wa.x; acc[1].y += za.y * wa.y; acc[1].z += za.y * wa.z; acc[1].w += za.y * wa.w;
        acc[2].x += za.z * wa.x; acc[2].y += za.z * wa.y; acc[2].z += za.z * wa.z; acc[2].w += za.z * wa.w;
        acc[3].x += za.w * wa.x; acc[3].y += za.w * wa.y; acc[3].z += za.w * wa.z; acc[3].w += za.w * wa.w;
    }

    float4 bb  = *(const float4*)(b  + 4 * lane);
    float4 al4 = *(const float4*)(al + 4 * lane);
    float4 ar4 = *(const float4*)(ar + 4 * lane);

#pragma unroll
    for (int n = 0; n < 4; n++) {
        int node = node0 + 4 * wrp + n;
        float4 v = acc[n];
        v.x += bb.x; v.y += bb.y; v.z += bb.z; v.w += bb.w;
        if (node < N)
            *(float4*)(g_Zp + (size_t)node * OH + 4 * lane) = v;
        float4 pl = make_float4(v.x * al4.x, v.y * al4.y, v.z * al4.z, v.w * al4.w);
        float4 pr = make_float4(v.x * ar4.x, v.y * ar4.y, v.z * ar4.z, v.w * ar4.w);
        pl = wred_sum(pl);
        pr = wred_sum(pr);
        if (lane == 0 && node < N) {
            *(float4*)(g_el + node * 4) = pl;
            *(float4*)(g_er + node * 4) = pr;
        }
    }
}

// ---- K2: per-edge logits + leaky_relu + segment max over dst ----------------
__global__ void k_logits(const void* __restrict__ idx, int E) {
    int e = blockIdx.x * blockDim.x + threadIdx.x;
    if (e >= E) return;
    int is64 = g_is64;
    long long s = ld_idx(idx, e, is64);
    long long d = ld_idx(idx, (long long)E + e, is64);
    float4 l = *(const float4*)(g_el + s * 4);
    float4 r = *(const float4*)(g_er + d * 4);
    float4 a;
    a.x = l.x + r.x; a.x = a.x > 0.f ? a.x : 0.01f * a.x;
    a.y = l.y + r.y; a.y = a.y > 0.f ? a.y : 0.01f * a.y;
    a.z = l.z + r.z; a.z = a.z > 0.f ? a.z : 0.01f * a.z;
    a.w = l.w + r.w; a.w = a.w > 0.f ? a.w : 0.01f * a.w;
    g_a[e] = a;
    unsigned* mb = g_m + d * 4;
    atomicMax(mb + 0, enc_ord(a.x));
    atomicMax(mb + 1, enc_ord(a.y));
    atomicMax(mb + 2, enc_ord(a.z));
    atomicMax(mb + 3, enc_ord(a.w));
}

// ---- K3: ex = exp(a - m[dst]); segment sum over dst --------------------------
__global__ void k_exp(const void* __restrict__ idx, int E) {
    int e = blockIdx.x * blockDim.x + threadIdx.x;
    if (e >= E) return;
    long long d = ld_idx(idx, (long long)E + e, g_is64);
    float4 a = g_a[e];
    const unsigned* mb = g_m + d * 4;
    float4 ex;
    ex.x = __expf(a.x - dec_ord(mb[0]));
    ex.y = __expf(a.y - dec_ord(mb[1]));
    ex.z = __expf(a.z - dec_ord(mb[2]));
    ex.w = __expf(a.w - dec_ord(mb[3]));
    g_a[e] = ex;
    float* sb = g_s + d * 4;
    atomicAdd(sb + 0, ex.x);
    atomicAdd(sb + 1, ex.y);
    atomicAdd(sb + 2, ex.z);
    atomicAdd(sb + 3, ex.w);
}

// ---- K4: out[src] += (ex/s[dst]) * Zp[dst]  (one warp per edge) --------------
// 32 lanes x float4 = 128 cols. A float4 of consecutive cols is one o x 4 heads,
// so the component-wise product with att4 is exactly right.
__global__ void k_scatter(const void* __restrict__ idx, float* __restrict__ out, int E) {
    long long gt = (long long)blockIdx.x * blockDim.x + threadIdx.x;
    int w    = (int)(gt >> 5);
    int lane = threadIdx.x & 31;
    if (w >= E) return;
    int is64 = g_is64;
    long long src = ld_idx(idx, w, is64);
    long long dst = ld_idx(idx, (long long)E + w, is64);
    float4 ex = g_a[w];
    float4 sv = *(const float4*)(g_s + dst * 4);
    float4 att = make_float4(ex.x / sv.x, ex.y / sv.y, ex.z / sv.z, ex.w / sv.w);
    float4 zp = *(const float4*)(g_Zp + (size_t)dst * OH + lane * 4);
    float4 msg = make_float4(zp.x * att.x, zp.y * att.y, zp.z * att.z, zp.w * att.w);
    float* p = out + (size_t)src * OH + lane * 4;
    asm volatile("red.global.add.v4.f32 [%0], {%1, %2, %3, %4};"
                 :: "l"(p), "f"(msg.x), "f"(msg.y), "f"(msg.z), "f"(msg.w)
                 : "memory");
}

// ---- launch ------------------------------------------------------------------
extern "C" void kernel_launch(void* const* d_in, const int* in_sizes, int n_in,
                              void* d_out, int out_size) {
    const void*  idx = d_in[0];
    const float* Z   = (const float*)d_in[2];
    const float* W   = (const float*)d_in[3];
    const float* b   = (const float*)d_in[4];
    const float* al  = (const float*)d_in[5];
    const float* ar  = (const float*)d_in[6];
    float* out = (float*)d_out;

    int E = in_sizes[0] / 2;
    int N = in_sizes[2] / 128;

    k_detect<<<1, 1>>>((const int*)idx, 1024);
    k_init<<<512, 256>>>(out, N);

    cudaFuncSetAttribute(k_gemm, cudaFuncAttributeMaxDynamicSharedMemorySize, 102400);
    k_gemm<<<(N + 63) / 64, 512, 102400>>>(Z, W, b, al, ar, N);

    int eb = (E + 255) / 256;
    k_logits<<<eb, 256>>>(idx, E);
    k_exp<<<eb, 256>>>(idx, E);

    long long threads = (long long)E * 32;
    int sb = (int)((threads + 255) / 256);
    k_scatter<<<sb, 256>>>(idx, out, E);
}

// round 2
// speedup vs baseline: 1.7809x; 1.7809x over previous
#include <cuda_runtime.h>

// ---------------------------------------------------------------------------
// GATConv: rst[src] += softmax_dst(leaky_relu(e_l[src]+e_r[dst])) * Zp[dst]
// N=50000, E=1.6M, IN=128, OUT=32, HEADS=4 (OUT*H = 128)
// Strategy: fused edge pass (no max; safe, |logit| << 88) + on-device CSR by
// src + register-accumulated gather-reduce (no output atomics).
// ---------------------------------------------------------------------------

#define NMAX 50016
#define EMAX 1600000
#define OH 128

// ---- scratch (static device globals) ---------------------------------------
__device__ float    g_Zp[(size_t)NMAX * OH];   // projected features   25.6 MB
__device__ float    g_el[NMAX * 4];            // left logits  [N,H]
__device__ float    g_er[NMAX * 4];            // right logits [N,H]
__device__ float    g_s [NMAX * 4];            // softmax denominators
__device__ float4   g_a [EMAX];                // per-edge exp values
__device__ int      g_deg[NMAX];               // src degree histogram
__device__ int      g_off[NMAX + 1];           // CSR offsets
__device__ int      g_cur[NMAX];               // placement cursors
__device__ int      g_bsum[128];               // scan block partials
__device__ int      g_edst[EMAX];              // CSR: dst per slot
__device__ float4   g_eatt[EMAX];              // CSR: normalized att per slot
__device__ int      g_is64;

// ---- helpers ----------------------------------------------------------------
__device__ __forceinline__ long long ld_idx(const void* idx, long long i, int is64) {
    if (is64) return ((const long long*)idx)[i];
    return (long long)((const int*)idx)[i];
}
__device__ __forceinline__ float4 wred_sum(float4 v) {
#pragma unroll
    for (int o = 16; o; o >>= 1) {
        v.x += __shfl_xor_sync(0xffffffffu, v.x, o);
        v.y += __shfl_xor_sync(0xffffffffu, v.y, o);
        v.z += __shfl_xor_sync(0xffffffffu, v.z, o);
        v.w += __shfl_xor_sync(0xffffffffu, v.w, o);
    }
    return v;
}

// ---- index width detection ----------------------------------------------------
__global__ void k_detect(const int* w, int nwords) {
    int ok = 1;
    for (int i = 1; i < nwords; i += 2)
        if (w[i] != 0) { ok = 0; break; }
    g_is64 = ok;
}

// ---- zero accumulators --------------------------------------------------------
__global__ void k_init(int N) {
    int i = blockIdx.x * blockDim.x + threadIdx.x;
    int stride = gridDim.x * blockDim.x;
    for (int j = i; j < N * 4; j += stride) g_s[j] = 0.0f;
    for (int j = i; j < N; j += stride) g_deg[j] = 0;
}

// ---- GEMM: Zp = Z @ W^T + b, fused e_l/e_r ------------------------------------
#define WTS 132
#define ZTS 68
__global__ void k_gemm(const float* __restrict__ Z, const float* __restrict__ W,
                       const float* __restrict__ b, const float* __restrict__ al,
                       const float* __restrict__ ar, int N) {
    extern __shared__ float sm[];
    float* Wt = sm;
    float* Zt = sm + 128 * WTS;

    const int tid = threadIdx.x;
    const int kc  = tid & 31;
    const int g   = tid >> 5;
    const int node0 = blockIdx.x * 64;

    for (int c = g; c < 128; c += 16) {
        float4 w4 = *(const float4*)(W + c * 128 + kc * 4);
        Wt[(4 * kc + 0) * WTS + c] = w4.x;
        Wt[(4 * kc + 1) * WTS + c] = w4.y;
        Wt[(4 * kc + 2) * WTS + c] = w4.z;
        Wt[(4 * kc + 3) * WTS + c] = w4.w;
    }
    for (int r = g; r < 64; r += 16) {
        int row = node0 + r; if (row >= N) row = N - 1;
        float4 z4 = *(const float4*)(Z + (size_t)row * 128 + kc * 4);
        Zt[(4 * kc + 0) * ZTS + r] = z4.x;
        Zt[(4 * kc + 1) * ZTS + r] = z4.y;
        Zt[(4 * kc + 2) * ZTS + r] = z4.z;
        Zt[(4 * kc + 3) * ZTS + r] = z4.w;
    }
    __syncthreads();

    const int lane = tid & 31;
    const int wrp  = tid >> 5;
    float4 acc[4];
#pragma unroll
    for (int n = 0; n < 4; n++) acc[n] = make_float4(0.f, 0.f, 0.f, 0.f);

    const float* wrow = Wt + 4 * lane;
    const float* zrow = Zt + 4 * wrp;
#pragma unroll 4
    for (int k = 0; k < 128; k++) {
        float4 wa = *(const float4*)(wrow + k * WTS);
        float4 za = *(const float4*)(zrow + k * ZTS);
        acc[0].x += za.x * wa.x; acc[0].y += za.x * wa.y; acc[0].z += za.x * wa.z; acc[0].w += za.x * wa.w;
        acc[1].x += za.y * wa.x; acc[1].y += za.y * wa.y; acc[1].z += za.y * wa.z; acc[1].w += za.y * wa.w;
        acc[2].x += za.z * wa.x; acc[2].y += za.z * wa.y; acc[2].z += za.z * wa.z; acc[2].w += za.z * wa.w;
        acc[3].x += za.w * wa.x; acc[3].y += za.w * wa.y; acc[3].z += za.w * wa.z; acc[3].w += za.w * wa.w;
    }

    float4 bb  = *(const float4*)(b  + 4 * lane);
    float4 al4 = *(const float4*)(al + 4 * lane);
    float4 ar4 = *(const float4*)(ar + 4 * lane);

#pragma unroll
    for (int n = 0; n < 4; n++) {
        int node = node0 + 4 * wrp + n;
        float4 v = acc[n];
        v.x += bb.x; v.y += bb.y; v.z += bb.z; v.w += bb.w;
        if (node < N)
            *(float4*)(g_Zp + (size_t)node * OH + 4 * lane) = v;
        float4 pl = make_float4(v.x * al4.x, v.y * al4.y, v.z * al4.z, v.w * al4.w);
        float4 pr = make_float4(v.x * ar4.x, v.y * ar4.y, v.z * ar4.z, v.w * ar4.w);
        pl = wred_sum(pl);
        pr = wred_sum(pr);
        if (lane == 0 && node < N) {
            *(float4*)(g_el + node * 4) = pl;
            *(float4*)(g_er + node * 4) = pr;
        }
    }
}

// ---- fused edge pass: logits + leaky_relu + exp + segment-sum + histogram -----
__global__ void k_fused(const void* __restrict__ idx, int E) {
    int e = blockIdx.x * blockDim.x + threadIdx.x;
    if (e >= E) return;
    int is64 = g_is64;
    long long s = ld_idx(idx, e, is64);
    long long d = ld_idx(idx, (long long)E + e, is64);
    float4 l = *(const float4*)(g_el + s * 4);
    float4 r = *(const float4*)(g_er + d * 4);
    float4 a;
    a.x = l.x + r.x; a.x = a.x > 0.f ? a.x : 0.01f * a.x;
    a.y = l.y + r.y; a.y = a.y > 0.f ? a.y : 0.01f * a.y;
    a.z = l.z + r.z; a.z = a.z > 0.f ? a.z : 0.01f * a.z;
    a.w = l.w + r.w; a.w = a.w > 0.f ? a.w : 0.01f * a.w;
    float4 ex;
    ex.x = __expf(a.x); ex.y = __expf(a.y); ex.z = __expf(a.z); ex.w = __expf(a.w);
    g_a[e] = ex;
    float* sb = g_s + d * 4;
    asm volatile("red.global.add.v4.f32 [%0], {%1, %2, %3, %4};"
                 :: "l"(sb), "f"(ex.x), "f"(ex.y), "f"(ex.z), "f"(ex.w) : "memory");
    atomicAdd(&g_deg[(int)s], 1);
}

// ---- scan stage 1: per-block sums (1024 elems/block) ---------------------------
__global__ void k_scan1(int N) {
    __shared__ int wsum[8];
    int b = blockIdx.x, t = threadIdx.x;
    int base = b * 1024 + t * 4;
    int sv = 0;
#pragma unroll
    for (int i = 0; i < 4; i++) if (base + i < N) sv += g_deg[base + i];
#pragma unroll
    for (int o = 16; o; o >>= 1) sv += __shfl_xor_sync(0xffffffffu, sv, o);
    if ((t & 31) == 0) wsum[t >> 5] = sv;
    __syncthreads();
    if (t == 0) {
        int tot = 0;
#pragma unroll
        for (int i = 0; i < 8; i++) tot += wsum[i];
        g_bsum[b] = tot;
    }
}

// ---- scan stage 2: exclusive scan of block sums (tiny) -------------------------
__global__ void k_scan2(int nb) {
    int s = 0;
    for (int i = 0; i < nb; i++) { int v = g_bsum[i]; g_bsum[i] = s; s += v; }
}

// ---- scan stage 3: local exclusive scan + offsets + cursors --------------------
__global__ void k_scan3(int N, int E) {
    __shared__ int wsum[8];
    int b = blockIdx.x, t = threadIdx.x;
    int lane = t & 31, w = t >> 5;
    int base = b * 1024 + t * 4;
    int v[4];
#pragma unroll
    for (int i = 0; i < 4; i++) v[i] = (base + i < N) ? g_deg[base + i] : 0;
    int tsum = v[0] + v[1] + v[2] + v[3];
    int x = tsum;
#pragma unroll
    for (int o = 1; o < 32; o <<= 1) {
        int y = __shfl_up_sync(0xffffffffu, x, o);
        if (lane >= o) x += y;
    }
    if (lane == 31) wsum[w] = x;
    __syncthreads();
    if (w == 0) {
        int y = (lane < 8) ? wsum[lane] : 0;
#pragma unroll
        for (int o = 1; o < 8; o <<= 1) {
            int z = __shfl_up_sync(0xffffffffu, y, o);
            if (lane >= o) y += z;
        }
        if (lane < 8) wsum[lane] = y;
    }
    __syncthreads();
    int run = x - tsum + (w ? wsum[w - 1] : 0) + g_bsum[b];
#pragma unroll
    for (int i = 0; i < 4; i++) {
        if (base + i < N) { g_off[base + i] = run; g_cur[base + i] = run; }
        run += v[i];
    }
    if (b == 0 && t == 0) g_off[N] = E;
}

// ---- placement: bucket edges by src, normalize attention -----------------------
__global__ void k_place(const void* __restrict__ idx, int E) {
    int e = blockIdx.x * blockDim.x + threadIdx.x;
    if (e >= E) return;
    int is64 = g_is64;
    long long s = ld_idx(idx, e, is64);
    long long d = ld_idx(idx, (long long)E + e, is64);
    float4 ex = g_a[e];
    float4 sv = *(const float4*)(g_s + d * 4);
    float4 att = make_float4(ex.x / sv.x, ex.y / sv.y, ex.z / sv.z, ex.w / sv.w);
    int pos = atomicAdd(&g_cur[(int)s], 1);
    g_edst[pos] = (int)d;
    g_eatt[pos] = att;
}

// ---- gather-reduce: one warp per node, accumulate in registers ------------------
__global__ void k_gather(float* __restrict__ out, int N) {
    int gw = (blockIdx.x * blockDim.x + threadIdx.x) >> 5;
    int lane = threadIdx.x & 31;
    if (gw >= N) return;
    int beg = g_off[gw], end = g_off[gw + 1];
    float4 acc = make_float4(0.f, 0.f, 0.f, 0.f);
    int j = beg;
    for (; j + 1 < end; j += 2) {
        int d0 = g_edst[j], d1 = g_edst[j + 1];
        float4 a0 = g_eatt[j], a1 = g_eatt[j + 1];
        float4 z0 = *(const float4*)(g_Zp + (size_t)d0 * OH + lane * 4);
        float4 z1 = *(const float4*)(g_Zp + (size_t)d1 * OH + lane * 4);
        acc.x += a0.x * z0.x + a1.x * z1.x;
        acc.y += a0.y * z0.y + a1.y * z1.y;
        acc.z += a0.z * z0.z + a1.z * z1.z;
        acc.w += a0.w * z0.w + a1.w * z1.w;
    }
    if (j < end) {
        int d0 = g_edst[j];
        float4 a0 = g_eatt[j];
        float4 z0 = *(const float4*)(g_Zp + (size_t)d0 * OH + lane * 4);
        acc.x += a0.x * z0.x; acc.y += a0.y * z0.y;
        acc.z += a0.z * z0.z; acc.w += a0.w * z0.w;
    }
    *(float4*)(out + (size_t)gw * OH + lane * 4) = acc;
}

// ---- launch ----------------------------------------------------------------------
extern "C" void kernel_launch(void* const* d_in, const int* in_sizes, int n_in,
                              void* d_out, int out_size) {
    const void*  idx = d_in[0];
    const float* Z   = (const float*)d_in[2];
    const float* W   = (const float*)d_in[3];
    const float* b   = (const float*)d_in[4];
    const float* al  = (const float*)d_in[5];
    const float* ar  = (const float*)d_in[6];
    float* out = (float*)d_out;

    int E = in_sizes[0] / 2;
    int N = in_sizes[2] / 128;
    int nb = (N + 1023) / 1024;

    k_detect<<<1, 1>>>((const int*)idx, 1024);
    k_init<<<256, 256>>>(N);

    cudaFuncSetAttribute(k_gemm, cudaFuncAttributeMaxDynamicSharedMemorySize, 102400);
    k_gemm<<<(N + 63) / 64, 512, 102400>>>(Z, W, b, al, ar, N);

    int eb = (E + 255) / 256;
    k_fused<<<eb, 256>>>(idx, E);

    k_scan1<<<nb, 256>>>(N);
    k_scan2<<<1, 1>>>(nb);
    k_scan3<<<nb, 256>>>(N, E);

    k_place<<<eb, 256>>>(idx, E);

    int gb = (N * 32 + 255) / 256;
    k_gather<<<gb, 256>>>(out, N);
}

// round 3
// speedup vs baseline: 1.8494x; 1.0385x over previous
#include <cuda_runtime.h>
#include <cuda_fp16.h>

// ---------------------------------------------------------------------------
// GATConv: rst[src] += softmax_dst(leaky_relu(e_l[src]+e_r[dst])) * Zp[dst]
// N=50000, E=1.6M, IN=128, OUT=32, HEADS=4 (OUT*H = 128)
// Pipeline: detect -> init -> hist(src) -> scan -> gemm(fp16 Zp out)
//           -> fused edge pass (exp + denom + direct CSR placement)
//           -> recip -> warp-per-node gather (fp16 rows, fp32 accum)
// ---------------------------------------------------------------------------

#define NMAX 50016
#define EMAX 1600000
#define OH 128

// ---- scratch ----------------------------------------------------------------
__device__ __half   g_Zph[(size_t)NMAX * OH];  // projected features fp16 12.8MB
__device__ float    g_el[NMAX * 4];            // left logits  [N,H]
__device__ float    g_er[NMAX * 4];            // right logits [N,H]
__device__ float    g_s [NMAX * 4];            // softmax denominators
__device__ float    g_sinv[NMAX * 4];          // 1/denominator
__device__ int      g_deg[NMAX];               // src degree histogram
__device__ int      g_off[NMAX + 1];           // CSR offsets
__device__ int      g_cur[NMAX];               // placement cursors
__device__ int      g_bsum[128];               // scan block partials
__device__ int4     g_slot[EMAX];              // CSR: {dst, half2 e01, half2 e23, pad}
__device__ int      g_is64;

// ---- helpers ------------------------------------------------------------------
__device__ __forceinline__ long long ld_idx(const void* idx, long long i, int is64) {
    if (is64) return ((const long long*)idx)[i];
    return (long long)((const int*)idx)[i];
}
__device__ __forceinline__ float4 wred_sum(float4 v) {
#pragma unroll
    for (int o = 16; o; o >>= 1) {
        v.x += __shfl_xor_sync(0xffffffffu, v.x, o);
        v.y += __shfl_xor_sync(0xffffffffu, v.y, o);
        v.z += __shfl_xor_sync(0xffffffffu, v.z, o);
        v.w += __shfl_xor_sync(0xffffffffu, v.w, o);
    }
    return v;
}

// ---- detect index width (parallel) ----------------------------------------------
__global__ void k_detect(const int* w) {
    int v = w[2 * threadIdx.x + 1];           // high word if int64
    int any = __syncthreads_or(v != 0);
    if (threadIdx.x == 0) g_is64 = !any;
}

// ---- zero accumulators -----------------------------------------------------------
__global__ void k_init(int N) {
    int i = blockIdx.x * blockDim.x + threadIdx.x;
    int stride = gridDim.x * blockDim.x;
    for (int j = i; j < N * 4; j += stride) g_s[j] = 0.0f;
    for (int j = i; j < N; j += stride) g_deg[j] = 0;
}

// ---- histogram of src degrees ------------------------------------------------------
__global__ void k_hist(const void* __restrict__ idx, int E) {
    int e = blockIdx.x * blockDim.x + threadIdx.x;
    if (e >= E) return;
    long long s = ld_idx(idx, e, g_is64);
    atomicAdd(&g_deg[(int)s], 1);
}

// ---- GEMM: Zp = Z @ W^T + b (fp16 store), fused e_l/e_r -----------------------------
#define WTS 132
#define ZTS 68
__global__ void k_gemm(const float* __restrict__ Z, const float* __restrict__ W,
                       const float* __restrict__ b, const float* __restrict__ al,
                       const float* __restrict__ ar, int N) {
    extern __shared__ float sm[];
    float* Wt = sm;
    float* Zt = sm + 128 * WTS;

    const int tid = threadIdx.x;
    const int kc  = tid & 31;
    const int g   = tid >> 5;
    const int node0 = blockIdx.x * 64;

    for (int c = g; c < 128; c += 16) {
        float4 w4 = *(const float4*)(W + c * 128 + kc * 4);
        Wt[(4 * kc + 0) * WTS + c] = w4.x;
        Wt[(4 * kc + 1) * WTS + c] = w4.y;
        Wt[(4 * kc + 2) * WTS + c] = w4.z;
        Wt[(4 * kc + 3) * WTS + c] = w4.w;
    }
    for (int r = g; r < 64; r += 16) {
        int row = node0 + r; if (row >= N) row = N - 1;
        float4 z4 = *(const float4*)(Z + (size_t)row * 128 + kc * 4);
        Zt[(4 * kc + 0) * ZTS + r] = z4.x;
        Zt[(4 * kc + 1) * ZTS + r] = z4.y;
        Zt[(4 * kc + 2) * ZTS + r] = z4.z;
        Zt[(4 * kc + 3) * ZTS + r] = z4.w;
    }
    __syncthreads();

    const int lane = tid & 31;
    const int wrp  = tid >> 5;
    float4 acc[4];
#pragma unroll
    for (int n = 0; n < 4; n++) acc[n] = make_float4(0.f, 0.f, 0.f, 0.f);

    const float* wrow = Wt + 4 * lane;
    const float* zrow = Zt + 4 * wrp;
#pragma unroll 4
    for (int k = 0; k < 128; k++) {
        float4 wa = *(const float4*)(wrow + k * WTS);
        float4 za = *(const float4*)(zrow + k * ZTS);
        acc[0].x += za.x * wa.x; acc[0].y += za.x * wa.y; acc[0].z += za.x * wa.z; acc[0].w += za.x * wa.w;
        acc[1].x += za.y * wa.x; acc[1].y += za.y * wa.y; acc[1].z += za.y * wa.z; acc[1].w += za.y * wa.w;
        acc[2].x += za.z * wa.x; acc[2].y += za.z * wa.y; acc[2].z += za.z * wa.z; acc[2].w += za.z * wa.w;
        acc[3].x += za.w * wa.x; acc[3].y += za.w * wa.y; acc[3].z += za.w * wa.z; acc[3].w += za.w * wa.w;
    }

    float4 bb  = *(const float4*)(b  + 4 * lane);
    float4 al4 = *(const float4*)(al + 4 * lane);
    float4 ar4 = *(const float4*)(ar + 4 * lane);

#pragma unroll
    for (int n = 0; n < 4; n++) {
        int node = node0 + 4 * wrp + n;
        float4 v = acc[n];
        v.x += bb.x; v.y += bb.y; v.z += bb.z; v.w += bb.w;
        if (node < N) {
            __half2 h0 = __floats2half2_rn(v.x, v.y);
            __half2 h1 = __floats2half2_rn(v.z, v.w);
            uint2 p;
            p.x = *reinterpret_cast<unsigned*>(&h0);
            p.y = *reinterpret_cast<unsigned*>(&h1);
            *(uint2*)(g_Zph + (size_t)node * OH + 4 * lane) = p;
        }
        float4 pl = make_float4(v.x * al4.x, v.y * al4.y, v.z * al4.z, v.w * al4.w);
        float4 pr = make_float4(v.x * ar4.x, v.y * ar4.y, v.z * ar4.z, v.w * ar4.w);
        pl = wred_sum(pl);
        pr = wred_sum(pr);
        if (lane == 0 && node < N) {
            *(float4*)(g_el + node * 4) = pl;
            *(float4*)(g_er + node * 4) = pr;
        }
    }
}

// ---- scan stage 1: per-block sums (1024 elems/block) --------------------------------
__global__ void k_scan1(int N) {
    __shared__ int wsum[8];
    int b = blockIdx.x, t = threadIdx.x;
    int base = b * 1024 + t * 4;
    int sv = 0;
#pragma unroll
    for (int i = 0; i < 4; i++) if (base + i < N) sv += g_deg[base + i];
#pragma unroll
    for (int o = 16; o; o >>= 1) sv += __shfl_xor_sync(0xffffffffu, sv, o);
    if ((t & 31) == 0) wsum[t >> 5] = sv;
    __syncthreads();
    if (t == 0) {
        int tot = 0;
#pragma unroll
        for (int i = 0; i < 8; i++) tot += wsum[i];
        g_bsum[b] = tot;
    }
}

// ---- scan stage 2 ---------------------------------------------------------------------
__global__ void k_scan2(int nb) {
    int s = 0;
    for (int i = 0; i < nb; i++) { int v = g_bsum[i]; g_bsum[i] = s; s += v; }
}

// ---- scan stage 3: local scan + offsets + cursors ---------------------------------------
__global__ void k_scan3(int N, int E) {
    __shared__ int wsum[8];
    int b = blockIdx.x, t = threadIdx.x;
    int lane = t & 31, w = t >> 5;
    int base = b * 1024 + t * 4;
    int v[4];
#pragma unroll
    for (int i = 0; i < 4; i++) v[i] = (base + i < N) ? g_deg[base + i] : 0;
    int tsum = v[0] + v[1] + v[2] + v[3];
    int x = tsum;
#pragma unroll
    for (int o = 1; o < 32; o <<= 1) {
        int y = __shfl_up_sync(0xffffffffu, x, o);
        if (lane >= o) x += y;
    }
    if (lane == 31) wsum[w] = x;
    __syncthreads();
    if (w == 0) {
        int y = (lane < 8) ? wsum[lane] : 0;
#pragma unroll
        for (int o = 1; o < 8; o <<= 1) {
            int z = __shfl_up_sync(0xffffffffu, y, o);
            if (lane >= o) y += z;
        }
        if (lane < 8) wsum[lane] = y;
    }
    __syncthreads();
    int run = x - tsum + (w ? wsum[w - 1] : 0) + g_bsum[b];
#pragma unroll
    for (int i = 0; i < 4; i++) {
        if (base + i < N) { g_off[base + i] = run; g_cur[base + i] = run; }
        run += v[i];
    }
    if (b == 0 && t == 0) g_off[N] = E;
}

// ---- fused edge pass: logits + exp + denom red + direct CSR placement --------------------
__global__ void k_fused(const void* __restrict__ idx, int E) {
    int e = blockIdx.x * blockDim.x + threadIdx.x;
    if (e >= E) return;
    int is64 = g_is64;
    long long s = ld_idx(idx, e, is64);
    long long d = ld_idx(idx, (long long)E + e, is64);
    float4 l = *(const float4*)(g_el + s * 4);
    float4 r = *(const float4*)(g_er + d * 4);
    float4 a;
    a.x = l.x + r.x; a.x = a.x > 0.f ? a.x : 0.01f * a.x;
    a.y = l.y + r.y; a.y = a.y > 0.f ? a.y : 0.01f * a.y;
    a.z = l.z + r.z; a.z = a.z > 0.f ? a.z : 0.01f * a.z;
    a.w = l.w + r.w; a.w = a.w > 0.f ? a.w : 0.01f * a.w;
    float4 ex;
    ex.x = __expf(a.x); ex.y = __expf(a.y); ex.z = __expf(a.z); ex.w = __expf(a.w);
    float* sb = g_s + d * 4;
    asm volatile("red.global.add.v4.f32 [%0], {%1, %2, %3, %4};"
                 :: "l"(sb), "f"(ex.x), "f"(ex.y), "f"(ex.z), "f"(ex.w) : "memory");
    int pos = atomicAdd(&g_cur[(int)s], 1);
    __half2 h01 = __floats2half2_rn(ex.x, ex.y);
    __half2 h23 = __floats2half2_rn(ex.z, ex.w);
    int4 slot;
    slot.x = (int)d;
    slot.y = *reinterpret_cast<int*>(&h01);
    slot.z = *reinterpret_cast<int*>(&h23);
    slot.w = 0;
    g_slot[pos] = slot;
}

// ---- reciprocal of denominators ------------------------------------------------------------
__global__ void k_recip(int N4) {
    int i = blockIdx.x * blockDim.x + threadIdx.x;
    if (i < N4) g_sinv[i] = 1.0f / g_s[i];
}

// ---- gather-reduce: one warp per node, fp16 rows, fp32 accum --------------------------------
__global__ void k_gather(float* __restrict__ out, int N) {
    int gw = (blockIdx.x * blockDim.x + threadIdx.x) >> 5;
    int lane = threadIdx.x & 31;
    if (gw >= N) return;
    int beg = g_off[gw], end = g_off[gw + 1];
    float4 acc = make_float4(0.f, 0.f, 0.f, 0.f);
    const __half* zbase = g_Zph;
    int j = beg;
    for (; j + 1 < end; j += 2) {
        int4 s0 = g_slot[j];
        int4 s1 = g_slot[j + 1];
        float4 si0 = *(const float4*)(g_sinv + s0.x * 4);
        float4 si1 = *(const float4*)(g_sinv + s1.x * 4);
        uint2 zh0 = *(const uint2*)(zbase + (size_t)s0.x * OH + lane * 4);
        uint2 zh1 = *(const uint2*)(zbase + (size_t)s1.x * OH + lane * 4);
        float2 e001 = __half22float2(*reinterpret_cast<__half2*>(&s0.y));
        float2 e023 = __half22float2(*reinterpret_cast<__half2*>(&s0.z));
        float2 e101 = __half22float2(*reinterpret_cast<__half2*>(&s1.y));
        float2 e123 = __half22float2(*reinterpret_cast<__half2*>(&s1.z));
        float2 z00 = __half22float2(*reinterpret_cast<__half2*>(&zh0.x));
        float2 z01 = __half22float2(*reinterpret_cast<__half2*>(&zh0.y));
        float2 z10 = __half22float2(*reinterpret_cast<__half2*>(&zh1.x));
        float2 z11 = __half22float2(*reinterpret_cast<__half2*>(&zh1.y));
        acc.x += (e001.x * si0.x) * z00.x + (e101.x * si1.x) * z10.x;
        acc.y += (e001.y * si0.y) * z00.y + (e101.y * si1.y) * z10.y;
        acc.z += (e023.x * si0.z) * z01.x + (e123.x * si1.z) * z11.x;
        acc.w += (e023.y * si0.w) * z01.y + (e123.y * si1.w) * z11.y;
    }
    if (j < end) {
        int4 s0 = g_slot[j];
        float4 si0 = *(const float4*)(g_sinv + s0.x * 4);
        uint2 zh0 = *(const uint2*)(zbase + (size_t)s0.x * OH + lane * 4);
        float2 e001 = __half22float2(*reinterpret_cast<__half2*>(&s0.y));
        float2 e023 = __half22float2(*reinterpret_cast<__half2*>(&s0.z));
        float2 z00 = __half22float2(*reinterpret_cast<__half2*>(&zh0.x));
        float2 z01 = __half22float2(*reinterpret_cast<__half2*>(&zh0.y));
        acc.x += (e001.x * si0.x) * z00.x;
        acc.y += (e001.y * si0.y) * z00.y;
        acc.z += (e023.x * si0.z) * z01.x;
        acc.w += (e023.y * si0.w) * z01.y;
    }
    *(float4*)(out + (size_t)gw * OH + lane * 4) = acc;
}

// ---- launch -----------------------------------------------------------------------------------
extern "C" void kernel_launch(void* const* d_in, const int* in_sizes, int n_in,
                              void* d_out, int out_size) {
    const void*  idx = d_in[0];
    const float* Z   = (const float*)d_in[2];
    const float* W   = (const float*)d_in[3];
    const float* b   = (const float*)d_in[4];
    const float* al  = (const float*)d_in[5];
    const float* ar  = (const float*)d_in[6];
    float* out = (float*)d_out;

    int E = in_sizes[0] / 2;
    int N = in_sizes[2] / 128;
    int nb = (N + 1023) / 1024;
    int eb = (E + 255) / 256;

    k_detect<<<1, 512>>>((const int*)idx);
    k_init<<<256, 256>>>(N);
    k_hist<<<eb, 256>>>(idx, E);
    k_scan1<<<nb, 256>>>(N);
    k_scan2<<<1, 1>>>(nb);
    k_scan3<<<nb, 256>>>(N, E);

    cudaFuncSetAttribute(k_gemm, cudaFuncAttributeMaxDynamicSharedMemorySize, 102400);
    k_gemm<<<(N + 63) / 64, 512, 102400>>>(Z, W, b, al, ar, N);

    k_fused<<<eb, 256>>>(idx, E);
    k_recip<<<(N * 4 + 255) / 256, 256>>>(N * 4);

    int gb = (N * 32 + 255) / 256;
    k_gather<<<gb, 256>>>(out, N);
}

// round 4
// speedup vs baseline: 3.1476x; 1.7019x over previous
#include <cuda_runtime.h>
#include <cuda_fp16.h>
#include <mma.h>

using namespace nvcuda;

// ---------------------------------------------------------------------------
// GATConv: rst[src] += softmax_dst(leaky_relu(e_l[src]+e_r[dst])) * Zp[dst]
// N=50000, E=1.6M, IN=128, OUT=32, HEADS=4 (OUT*H = 128)
// ---------------------------------------------------------------------------

#define NMAX 50016
#define EMAX 1600000
#define OH 128

// ---- scratch ----------------------------------------------------------------
__device__ __half   g_Zph[(size_t)NMAX * OH];  // projected (later: /s) fp16
__device__ float    g_el[NMAX * 4];
__device__ float    g_er[NMAX * 4];
__device__ float    g_s [NMAX * 4];            // softmax denominators
__device__ int      g_deg[NMAX];
__device__ int      g_off[NMAX + 1];
__device__ int      g_cur[NMAX];
__device__ int      g_bsum[128];
__device__ int4     g_slot[EMAX];              // {dst, half2 e01, half2 e23, 0}
__device__ int      g_is64;

// ---- helpers ------------------------------------------------------------------
__device__ __forceinline__ long long ld_idx(const void* idx, long long i, int is64) {
    if (is64) return ((const long long*)idx)[i];
    return (long long)((const int*)idx)[i];
}
__device__ __forceinline__ float4 wred_sum(float4 v) {
#pragma unroll
    for (int o = 16; o; o >>= 1) {
        v.x += __shfl_xor_sync(0xffffffffu, v.x, o);
        v.y += __shfl_xor_sync(0xffffffffu, v.y, o);
        v.z += __shfl_xor_sync(0xffffffffu, v.z, o);
        v.w += __shfl_xor_sync(0xffffffffu, v.w, o);
    }
    return v;
}

// ---- detect index width ----------------------------------------------------------
__global__ void k_detect(const int* w) {
    int v = w[2 * threadIdx.x + 1];
    int any = __syncthreads_or(v != 0);
    if (threadIdx.x == 0) g_is64 = !any;
}

// ---- zero accumulators -------------------------------------------------------------
__global__ void k_init(int N) {
    int i = blockIdx.x * blockDim.x + threadIdx.x;
    int stride = gridDim.x * blockDim.x;
    for (int j = i; j < N * 4; j += stride) g_s[j] = 0.0f;
    for (int j = i; j < N; j += stride) g_deg[j] = 0;
}

// ---- histogram of src degrees --------------------------------------------------------
__global__ void k_hist(const void* __restrict__ idx, int E) {
    int e = blockIdx.x * blockDim.x + threadIdx.x;
    if (e >= E) return;
    long long s = ld_idx(idx, e, g_is64);
    atomicAdd(&g_deg[(int)s], 1);
}

// ---- tensor-core GEMM: Zp = Z @ W^T + b (fp16 store), fused e_l/e_r ------------------
// Block 256 threads (8 warps), tile 64 nodes x 128 cols, K=128.
// SMEM phase1: Wh[128][136] fp16 (34816 B) + Zh[64][136] fp16 (17408 B) = 52224 B
// SMEM phase2: Cs[64][132] fp32 (33792 B), reusing the same buffer.
#define GW 136
#define CW 132
#define GEMM_SMEM 52224
__global__ void k_gemm_mma(const float* __restrict__ Z, const float* __restrict__ W,
                           const float* __restrict__ b, const float* __restrict__ al,
                           const float* __restrict__ ar, int N) {
    extern __shared__ char smraw[];
    __half* Wh = (__half*)smraw;
    __half* Zh = (__half*)(smraw + 128 * GW * 2);
    float*  Cs = (float*)smraw;

    const int tid = threadIdx.x;
    const int node0 = blockIdx.x * 64;

    // W [c][k] row-major -> fp16
    for (int i = tid; i < 128 * 32; i += 256) {
        int c = i >> 5, kq = i & 31;
        float4 w4 = *(const float4*)(W + c * 128 + kq * 4);
        __half2 h0 = __floats2half2_rn(w4.x, w4.y);
        __half2 h1 = __floats2half2_rn(w4.z, w4.w);
        *(uint2*)(Wh + c * GW + kq * 4) =
            make_uint2(*reinterpret_cast<unsigned*>(&h0), *reinterpret_cast<unsigned*>(&h1));
    }
    // Z tile [r][k] row-major -> fp16
    for (int i = tid; i < 64 * 32; i += 256) {
        int r = i >> 5, kq = i & 31;
        int row = node0 + r; if (row >= N) row = N - 1;
        float4 z4 = *(const float4*)(Z + (size_t)row * 128 + kq * 4);
        __half2 h0 = __floats2half2_rn(z4.x, z4.y);
        __half2 h1 = __floats2half2_rn(z4.z, z4.w);
        *(uint2*)(Zh + r * GW + kq * 4) =
            make_uint2(*reinterpret_cast<unsigned*>(&h0), *reinterpret_cast<unsigned*>(&h1));
    }
    __syncthreads();

    const int w  = tid >> 5;
    const int wr = w >> 1;      // 0..3 -> 16-row band
    const int wc = w & 1;       // 0..1 -> 64-col band

    wmma::fragment<wmma::accumulator, 16, 16, 16, float> acc[4];
#pragma unroll
    for (int c = 0; c < 4; c++) wmma::fill_fragment(acc[c], 0.0f);

#pragma unroll
    for (int k = 0; k < 128; k += 16) {
        wmma::fragment<wmma::matrix_a, 16, 16, 16, __half, wmma::row_major> af;
        wmma::load_matrix_sync(af, Zh + (wr * 16) * GW + k, GW);
#pragma unroll
        for (int c = 0; c < 4; c++) {
            wmma::fragment<wmma::matrix_b, 16, 16, 16, __half, wmma::col_major> bf;
            wmma::load_matrix_sync(bf, Wh + (wc * 64 + c * 16) * GW + k, GW);
            wmma::mma_sync(acc[c], af, bf, acc[c]);
        }
    }
    __syncthreads();   // done reading Wh/Zh; safe to overwrite with Cs
#pragma unroll
    for (int c = 0; c < 4; c++)
        wmma::store_matrix_sync(Cs + (wr * 16) * CW + wc * 64 + c * 16, acc[c], CW,
                                wmma::mem_row_major);
    __syncthreads();

    // epilogue: warp w handles rows w*8 .. w*8+7; lane = o, 4 heads per lane
    const int lane = tid & 31;
    float4 bb  = *(const float4*)(b  + 4 * lane);
    float4 al4 = *(const float4*)(al + 4 * lane);
    float4 ar4 = *(const float4*)(ar + 4 * lane);

#pragma unroll
    for (int rr = 0; rr < 8; rr++) {
        int r = w * 8 + rr;
        int node = node0 + r;
        float4 v = *(const float4*)(Cs + r * CW + lane * 4);
        v.x += bb.x; v.y += bb.y; v.z += bb.z; v.w += bb.w;
        if (node < N) {
            __half2 h0 = __floats2half2_rn(v.x, v.y);
            __half2 h1 = __floats2half2_rn(v.z, v.w);
            *(uint2*)(g_Zph + (size_t)node * OH + 4 * lane) =
                make_uint2(*reinterpret_cast<unsigned*>(&h0), *reinterpret_cast<unsigned*>(&h1));
        }
        float4 pl = make_float4(v.x * al4.x, v.y * al4.y, v.z * al4.z, v.w * al4.w);
        float4 pr = make_float4(v.x * ar4.x, v.y * ar4.y, v.z * ar4.z, v.w * ar4.w);
        pl = wred_sum(pl);
        pr = wred_sum(pr);
        if (lane == 0 && node < N) {
            *(float4*)(g_el + node * 4) = pl;
            *(float4*)(g_er + node * 4) = pr;
        }
    }
}

// ---- scan stage 1 ----------------------------------------------------------------------
__global__ void k_scan1(int N) {
    __shared__ int wsum[8];
    int b = blockIdx.x, t = threadIdx.x;
    int base = b * 1024 + t * 4;
    int sv = 0;
#pragma unroll
    for (int i = 0; i < 4; i++) if (base + i < N) sv += g_deg[base + i];
#pragma unroll
    for (int o = 16; o; o >>= 1) sv += __shfl_xor_sync(0xffffffffu, sv, o);
    if ((t & 31) == 0) wsum[t >> 5] = sv;
    __syncthreads();
    if (t == 0) {
        int tot = 0;
#pragma unroll
        for (int i = 0; i < 8; i++) tot += wsum[i];
        g_bsum[b] = tot;
    }
}

// ---- scan stage 2 ------------------------------------------------------------------------
__global__ void k_scan2(int nb) {
    int s = 0;
    for (int i = 0; i < nb; i++) { int v = g_bsum[i]; g_bsum[i] = s; s += v; }
}

// ---- scan stage 3 -------------------------------------------------------------------------
__global__ void k_scan3(int N, int E) {
    __shared__ int wsum[8];
    int b = blockIdx.x, t = threadIdx.x;
    int lane = t & 31, w = t >> 5;
    int base = b * 1024 + t * 4;
    int v[4];
#pragma unroll
    for (int i = 0; i < 4; i++) v[i] = (base + i < N) ? g_deg[base + i] : 0;
    int tsum = v[0] + v[1] + v[2] + v[3];
    int x = tsum;
#pragma unroll
    for (int o = 1; o < 32; o <<= 1) {
        int y = __shfl_up_sync(0xffffffffu, x, o);
        if (lane >= o) x += y;
    }
    if (lane == 31) wsum[w] = x;
    __syncthreads();
    if (w == 0) {
        int y = (lane < 8) ? wsum[lane] : 0;
#pragma unroll
        for (int o = 1; o < 8; o <<= 1) {
            int z = __shfl_up_sync(0xffffffffu, y, o);
            if (lane >= o) y += z;
        }
        if (lane < 8) wsum[lane] = y;
    }
    __syncthreads();
    int run = x - tsum + (w ? wsum[w - 1] : 0) + g_bsum[b];
#pragma unroll
    for (int i = 0; i < 4; i++) {
        if (base + i < N) { g_off[base + i] = run; g_cur[base + i] = run; }
        run += v[i];
    }
    if (b == 0 && t == 0) g_off[N] = E;
}

// ---- fused edge pass: logits + exp + denom red + direct CSR placement ---------------------
__global__ void k_fused(const void* __restrict__ idx, int E) {
    int e = blockIdx.x * blockDim.x + threadIdx.x;
    if (e >= E) return;
    int is64 = g_is64;
    long long s = ld_idx(idx, e, is64);
    long long d = ld_idx(idx, (long long)E + e, is64);
    float4 l = *(const float4*)(g_el + s * 4);
    float4 r = *(const float4*)(g_er + d * 4);
    float4 a;
    a.x = l.x + r.x; a.x = a.x > 0.f ? a.x : 0.01f * a.x;
    a.y = l.y + r.y; a.y = a.y > 0.f ? a.y : 0.01f * a.y;
    a.z = l.z + r.z; a.z = a.z > 0.f ? a.z : 0.01f * a.z;
    a.w = l.w + r.w; a.w = a.w > 0.f ? a.w : 0.01f * a.w;
    float4 ex;
    ex.x = __expf(a.x); ex.y = __expf(a.y); ex.z = __expf(a.z); ex.w = __expf(a.w);
    float* sb = g_s + d * 4;
    asm volatile("red.global.add.v4.f32 [%0], {%1, %2, %3, %4};"
                 :: "l"(sb), "f"(ex.x), "f"(ex.y), "f"(ex.z), "f"(ex.w) : "memory");
    int pos = atomicAdd(&g_cur[(int)s], 1);
    __half2 h01 = __floats2half2_rn(ex.x, ex.y);
    __half2 h23 = __floats2half2_rn(ex.z, ex.w);
    int4 slot;
    slot.x = (int)d;
    slot.y = *reinterpret_cast<int*>(&h01);
    slot.z = *reinterpret_cast<int*>(&h23);
    slot.w = 0;
    g_slot[pos] = slot;
}

// ---- fold 1/s into Zp: Zp'[d][o,h] = Zp[d][o,h] / s[d][h] -----------------------------------
__global__ void k_scale(int N) {
    int t = blockIdx.x * blockDim.x + threadIdx.x;
    int node = t >> 5, lane = t & 31;
    if (node >= N) return;
    float4 s4 = *(const float4*)(g_s + node * 4);
    float ix = __fdividef(1.f, s4.x), iy = __fdividef(1.f, s4.y);
    float iz = __fdividef(1.f, s4.z), iw = __fdividef(1.f, s4.w);
    __half* p = g_Zph + (size_t)node * OH + lane * 4;
    uint2 z = *(uint2*)p;
    float2 lo = __half22float2(*reinterpret_cast<__half2*>(&z.x));
    float2 hi = __half22float2(*reinterpret_cast<__half2*>(&z.y));
    lo.x *= ix; lo.y *= iy; hi.x *= iz; hi.y *= iw;
    __half2 h0 = __floats2half2_rn(lo.x, lo.y);
    __half2 h1 = __floats2half2_rn(hi.x, hi.y);
    *(uint2*)p = make_uint2(*reinterpret_cast<unsigned*>(&h0), *reinterpret_cast<unsigned*>(&h1));
}

// ---- gather-reduce: one warp per node, 4x unrolled for MLP -----------------------------------
__global__ void k_gather(float* __restrict__ out, int N) {
    int gw = (blockIdx.x * blockDim.x + threadIdx.x) >> 5;
    int lane = threadIdx.x & 31;
    if (gw >= N) return;
    int beg = g_off[gw], end = g_off[gw + 1];
    float4 acc = make_float4(0.f, 0.f, 0.f, 0.f);
    const __half* zb = g_Zph;
    int j = beg;
    for (; j + 3 < end; j += 4) {
        int4 s0 = g_slot[j];
        int4 s1 = g_slot[j + 1];
        int4 s2 = g_slot[j + 2];
        int4 s3 = g_slot[j + 3];
        uint2 z0 = *(const uint2*)(zb + (size_t)s0.x * OH + lane * 4);
        uint2 z1 = *(const uint2*)(zb + (size_t)s1.x * OH + lane * 4);
        uint2 z2 = *(const uint2*)(zb + (size_t)s2.x * OH + lane * 4);
        uint2 z3 = *(const uint2*)(zb + (size_t)s3.x * OH + lane * 4);
#define ACC(S, Z0, Z1)                                                    \
        {                                                                 \
            float2 e01 = __half22float2(*reinterpret_cast<__half2*>(&S.y));\
            float2 e23 = __half22float2(*reinterpret_cast<__half2*>(&S.z));\
            float2 a0 = __half22float2(*reinterpret_cast<__half2*>(&Z0)); \
            float2 a1 = __half22float2(*reinterpret_cast<__half2*>(&Z1)); \
            acc.x += e01.x * a0.x;  acc.y += e01.y * a0.y;                \
            acc.z += e23.x * a1.x;  acc.w += e23.y * a1.y;                \
        }
        ACC(s0, z0.x, z0.y); ACC(s1, z1.x, z1.y);
        ACC(s2, z2.x, z2.y); ACC(s3, z3.x, z3.y);
    }
    for (; j < end; j++) {
        int4 s0 = g_slot[j];
        uint2 z0 = *(const uint2*)(zb + (size_t)s0.x * OH + lane * 4);
        ACC(s0, z0.x, z0.y);
    }
#undef ACC
    *(float4*)(out + (size_t)gw * OH + lane * 4) = acc;
}

// ---- second stream for capture fork (created before harness checkpoints) --------------------
struct StreamHolder {
    cudaStream_t s2 = nullptr;
    cudaEvent_t evF = nullptr, evJ = nullptr;
    bool ok = false;
    StreamHolder() {
        ok = (cudaStreamCreateWithFlags(&s2, cudaStreamNonBlocking) == cudaSuccess) &&
             (cudaEventCreateWithFlags(&evF, cudaEventDisableTiming) == cudaSuccess) &&
             (cudaEventCreateWithFlags(&evJ, cudaEventDisableTiming) == cudaSuccess);
    }
};
static StreamHolder g_sh;

// ---- launch -----------------------------------------------------------------------------------
extern "C" void kernel_launch(void* const* d_in, const int* in_sizes, int n_in,
                              void* d_out, int out_size) {
    const void*  idx = d_in[0];
    const float* Z   = (const float*)d_in[2];
    const float* W   = (const float*)d_in[3];
    const float* b   = (const float*)d_in[4];
    const float* al  = (const float*)d_in[5];
    const float* ar  = (const float*)d_in[6];
    float* out = (float*)d_out;

    int E = in_sizes[0] / 2;
    int N = in_sizes[2] / 128;
    int nb = (N + 1023) / 1024;
    int eb = (E + 255) / 256;

    k_detect<<<1, 512>>>((const int*)idx);

    bool fork = g_sh.ok;
    cudaStream_t sb = fork ? g_sh.s2 : (cudaStream_t)0;
    if (fork) {
        cudaEventRecord(g_sh.evF, 0);
        cudaStreamWaitEvent(sb, g_sh.evF, 0);
    }
    // index-side chain (stream sb)
    k_init <<<256, 256, 0, sb>>>(N);
    k_hist <<<eb, 256, 0, sb>>>(idx, E);
    k_scan1<<<nb, 256, 0, sb>>>(N);
    k_scan2<<<1, 1, 0, sb>>>(nb);
    k_scan3<<<nb, 256, 0, sb>>>(N, E);

    // feature-side GEMM (default stream, concurrent with index chain)
    cudaFuncSetAttribute(k_gemm_mma, cudaFuncAttributeMaxDynamicSharedMemorySize, GEMM_SMEM);
    k_gemm_mma<<<(N + 63) / 64, 256, GEMM_SMEM>>>(Z, W, b, al, ar, N);

    if (fork) {
        cudaEventRecord(g_sh.evJ, sb);
        cudaStreamWaitEvent(0, g_sh.evJ, 0);
    }

    k_fused<<<eb, 256>>>(idx, E);
    k_scale<<<(N * 32 + 255) / 256, 256>>>(N);
    k_gather<<<(N * 32 + 255) / 256, 256>>>(out, N);
}